// round 16
// baseline (speedup 1.0000x reference)
#include <cuda_runtime.h>
#include <cuda_bf16.h>
#include <cuda_fp16.h>
#include <cstdint>

#define T_SEQ 4096
#define NHEAD 12
#define HD    64
#define CDIM  768
#define K3    (3*CDIM)

typedef unsigned int u32;

// ---- base-target helpers (sm_80+ PTX, no 'a' suffix) ----------------------
__device__ __forceinline__ u32 smem_u32(const void* p) {
  u32 a;
  asm("{ .reg .u64 t; cvta.to.shared.u64 t, %1; cvt.u32.u64 %0, t; }"
      : "=r"(a) : "l"(p));
  return a;
}
__device__ __forceinline__ void cpasync16(u32 dst, const void* src) {
  asm volatile("cp.async.ca.shared.global [%0], [%1], 16;"
               :: "r"(dst), "l"(src) : "memory");
}
#define CP_COMMIT() asm volatile("cp.async.commit_group;" ::: "memory")
#define LDSM4(R, addr)                                                        \
  asm volatile("ldmatrix.sync.aligned.m8n8.x4.shared.b16 {%0,%1,%2,%3}, [%4];"\
               : "=r"((R)[0]), "=r"((R)[1]), "=r"((R)[2]), "=r"((R)[3])       \
               : "r"(addr))
__device__ __forceinline__ void mma_bf16(float* c, const u32* a, u32 b0, u32 b1) {
  asm volatile(
      "mma.sync.aligned.m16n8k16.row.col.f32.bf16.bf16.f32 "
      "{%0,%1,%2,%3}, {%4,%5,%6,%7}, {%8,%9}, {%0,%1,%2,%3};"
      : "+f"(c[0]), "+f"(c[1]), "+f"(c[2]), "+f"(c[3])
      : "r"(a[0]), "r"(a[1]), "r"(a[2]), "r"(a[3]), "r"(b0), "r"(b1));
}
__device__ __forceinline__ void mma_f16(float* c, const u32* a, u32 b0, u32 b1) {
  asm volatile(
      "mma.sync.aligned.m16n8k16.row.col.f32.f16.f16.f32 "
      "{%0,%1,%2,%3}, {%4,%5,%6,%7}, {%8,%9}, {%0,%1,%2,%3};"
      : "+f"(c[0]), "+f"(c[1]), "+f"(c[2]), "+f"(c[3])
      : "r"(a[0]), "r"(a[1]), "r"(a[2]), "r"(a[3]), "r"(b0), "r"(b1));
}
// pack two fp32 into bf16x2 register (lo = first arg)
__device__ __forceinline__ u32 packbf2(float lo, float hi) {
  u32 r;
  asm("cvt.rn.bf16x2.f32 %0, %1, %2;" : "=r"(r) : "f"(hi), "f"(lo));
  return r;
}

// ---- scratch --------------------------------------------------------------
__device__ float g_qkv[T_SEQ * K3];
__device__ __half g_xh[T_SEQ * CDIM], g_xl[T_SEQ * CDIM];
__device__ __half g_wah[K3 * CDIM],  g_wal[K3 * CDIM];            // [N][K] fp16
__device__ __nv_bfloat16 g_wph[CDIM * CDIM], g_wpl[CDIM * CDIM];  // [N][K] bf16
__device__ __half g_qh[NHEAD * T_SEQ * HD], g_ql[NHEAD * T_SEQ * HD];  // [h][t][d]
__device__ __half g_kh[NHEAD * T_SEQ * HD], g_kl[NHEAD * T_SEQ * HD];  // [h][t][d]
__device__ __nv_bfloat16 g_vbh[NHEAD * HD * T_SEQ], g_vbl[NHEAD * HD * T_SEQ]; // [h][d][t]
__device__ __nv_bfloat16 g_yh[T_SEQ * CDIM], g_yl[T_SEQ * CDIM];

// ---------------------------------------------------------------------------
// split fp32 -> (hi, lo) fp16
// ---------------------------------------------------------------------------
__global__ __launch_bounds__(256) void split_f16(
    const float* __restrict__ in, __half* __restrict__ oh,
    __half* __restrict__ ol, int n4)
{
  int i = blockIdx.x * 256 + threadIdx.x;
  if (i >= n4) return;
  float4 v = ((const float4*)in)[i];
  __half h0 = __float2half(v.x), h1 = __float2half(v.y);
  __half h2 = __float2half(v.z), h3 = __float2half(v.w);
  __half l0 = __float2half(v.x - __half2float(h0));
  __half l1 = __float2half(v.y - __half2float(h1));
  __half l2 = __float2half(v.z - __half2float(h2));
  __half l3 = __float2half(v.w - __half2float(h3));
  ((__half2*)oh)[2 * i + 0] = __half2(h0, h1);
  ((__half2*)oh)[2 * i + 1] = __half2(h2, h3);
  ((__half2*)ol)[2 * i + 0] = __half2(l0, l1);
  ((__half2*)ol)[2 * i + 1] = __half2(l2, l3);
}

// ---------------------------------------------------------------------------
// transpose + split fp16: w[K][N] -> out[N][K] (hi, lo)
// ---------------------------------------------------------------------------
__global__ __launch_bounds__(256) void transpose_split_f16(
    const float* __restrict__ w, __half* __restrict__ oh,
    __half* __restrict__ ol, int K, int N)
{
  __shared__ float t[32][33];
  int n0 = blockIdx.x * 32, k0 = blockIdx.y * 32;
  int tx = threadIdx.x, ty = threadIdx.y;
#pragma unroll
  for (int i = ty; i < 32; i += 8)
    t[i][tx] = w[(size_t)(k0 + i) * N + n0 + tx];
  __syncthreads();
#pragma unroll
  for (int i = ty; i < 32; i += 8) {
    float v = t[tx][i];
    __half h = __float2half(v);
    __half l = __float2half(v - __half2float(h));
    oh[(size_t)(n0 + i) * K + k0 + tx] = h;
    ol[(size_t)(n0 + i) * K + k0 + tx] = l;
  }
}

// ---------------------------------------------------------------------------
// transpose + split bf16: w[K][N] -> out[N][K] (hi, lo) bf16
// ---------------------------------------------------------------------------
__global__ __launch_bounds__(256) void transpose_split_bf16(
    const float* __restrict__ w, __nv_bfloat16* __restrict__ oh,
    __nv_bfloat16* __restrict__ ol, int K, int N)
{
  __shared__ float t[32][33];
  int n0 = blockIdx.x * 32, k0 = blockIdx.y * 32;
  int tx = threadIdx.x, ty = threadIdx.y;
#pragma unroll
  for (int i = ty; i < 32; i += 8)
    t[i][tx] = w[(size_t)(k0 + i) * N + n0 + tx];
  __syncthreads();
#pragma unroll
  for (int i = ty; i < 32; i += 8) {
    float v = t[tx][i];
    __nv_bfloat16 h = __float2bfloat16(v);
    __nv_bfloat16 l = __float2bfloat16(v - __bfloat162float(h));
    oh[(size_t)(n0 + i) * K + k0 + tx] = h;
    ol[(size_t)(n0 + i) * K + k0 + tx] = l;
  }
}

// ---------------------------------------------------------------------------
// 16-bit 3-term GEMM: 2-stage cp.async, TERM-MAJOR mma ordering, 2 CTAs/SM.
// CTA 128x128, 8 warps (32x64), BK=32, 80B rows.
// ---------------------------------------------------------------------------
#define GSTAGE 40960
#define GEMM_SMEM (2 * GSTAGE)

#define GEMM_BODY(T16, MMA)                                                   \
  extern __shared__ char smem[];                                              \
  const u32 sb = smem_u32(smem);                                              \
  const int tid = threadIdx.x, lane = tid & 31, wid = tid >> 5;               \
  const int m0 = blockIdx.y << 7, n0 = blockIdx.x << 7;                       \
  const int wm = wid >> 1, wn = wid & 1;                                      \
  const T16* srcs[4] = {Ah, Al, Bh, Bl};                                      \
  float acc[2][8][4] = {};                                                    \
  const int nchunks = K >> 5;                                                 \
  auto load_stage = [&](int st, int k0) {                                     \
    u32 base = sb + st * GSTAGE;                                              \
    _Pragma("unroll")                                                         \
    for (int i = 0; i < 8; ++i) {                                             \
      int idx = tid + (i << 8);                                               \
      int ten = idx >> 9, u = idx & 511;                                      \
      int row = u >> 2, q = u & 3;                                            \
      int gr = (ten < 2 ? m0 : n0) + row;                                     \
      cpasync16(base + ten * 10240 + row * 80 + q * 16,                       \
                &srcs[ten][(size_t)gr * K + k0 + q * 8]);                     \
    }                                                                         \
    CP_COMMIT();                                                              \
  };                                                                          \
  load_stage(0, 0);                                                           \
  for (int c = 0; c < nchunks; ++c) {                                         \
    const bool pf = (c + 1 < nchunks);                                        \
    if (pf) load_stage((c + 1) & 1, (c + 1) << 5);                            \
    if (pf) asm volatile("cp.async.wait_group 1;" ::: "memory");              \
    else    asm volatile("cp.async.wait_group 0;" ::: "memory");              \
    __syncthreads();                                                          \
    const u32 base = sb + (c & 1) * GSTAGE;                                   \
    const u32 aA = base, aAl = base + 10240, aB = base + 20480,               \
              aBl = base + 30720;                                             \
    _Pragma("unroll")                                                         \
    for (int ks = 0; ks < 32; ks += 16) {                                     \
      const int arow = lane & 15, asel = lane >> 4;                           \
      u32 ah[2][4], al[2][4];                                                 \
      _Pragma("unroll")                                                       \
      for (int mt = 0; mt < 2; ++mt) {                                        \
        u32 off = (u32)((wm * 32 + mt * 16 + arow) * 80 +                     \
                        (ks + asel * 8) * 2);                                 \
        LDSM4(ah[mt], aA + off);                                              \
        LDSM4(al[mt], aAl + off);                                             \
      }                                                                       \
      const int nrow = (lane & 7) + ((lane >> 4) << 3);                       \
      const int koff = ks + (((lane >> 3) & 1) << 3);                         \
      u32 bh[4][4], bl[4][4];                                                 \
      _Pragma("unroll")                                                       \
      for (int ng = 0; ng < 4; ++ng) {                                        \
        u32 off = (u32)((wn * 64 + ng * 16 + nrow) * 80 + koff * 2);          \
        LDSM4(bh[ng], aB + off);                                              \
        LDSM4(bl[ng], aBl + off);                                             \
      }                                                                       \
      /* term-major: all h.h, then all h.l, then all l.h (per-acc order kept) */ \
      _Pragma("unroll")                                                       \
      for (int mt = 0; mt < 2; ++mt)                                          \
        _Pragma("unroll")                                                     \
        for (int nt = 0; nt < 8; ++nt) {                                      \
          const int ng = nt >> 1, sel = (nt & 1) << 1;                        \
          MMA(acc[mt][nt], ah[mt], bh[ng][sel], bh[ng][sel + 1]);             \
        }                                                                     \
      _Pragma("unroll")                                                       \
      for (int mt = 0; mt < 2; ++mt)                                          \
        _Pragma("unroll")                                                     \
        for (int nt = 0; nt < 8; ++nt) {                                      \
          const int ng = nt >> 1, sel = (nt & 1) << 1;                        \
          MMA(acc[mt][nt], ah[mt], bl[ng][sel], bl[ng][sel + 1]);             \
        }                                                                     \
      _Pragma("unroll")                                                       \
      for (int mt = 0; mt < 2; ++mt)                                          \
        _Pragma("unroll")                                                     \
        for (int nt = 0; nt < 8; ++nt) {                                      \
          const int ng = nt >> 1, sel = (nt & 1) << 1;                        \
          MMA(acc[mt][nt], al[mt], bh[ng][sel], bh[ng][sel + 1]);             \
        }                                                                     \
    }                                                                         \
    __syncthreads();                                                          \
  }                                                                           \
  const int rbase = m0 + wm * 32 + (lane >> 2);                               \
  const int cbase = n0 + wn * 64 + ((lane & 3) << 1);                         \
  _Pragma("unroll")                                                           \
  for (int mt = 0; mt < 2; ++mt)                                              \
    _Pragma("unroll")                                                         \
    for (int nt = 0; nt < 8; ++nt) {                                          \
      int row = rbase + mt * 16;                                              \
      int col = cbase + nt * 8;                                               \
      float b0 = bias[col], b1 = bias[col + 1];                               \
      *(float2*)&C[(size_t)row * N + col] =                                   \
          make_float2(acc[mt][nt][0] + b0, acc[mt][nt][1] + b1);              \
      *(float2*)&C[(size_t)(row + 8) * N + col] =                             \
          make_float2(acc[mt][nt][2] + b0, acc[mt][nt][3] + b1);              \
    }

__global__ __launch_bounds__(256, 2) void gemm_f16(
    const __half* __restrict__ Ah, const __half* __restrict__ Al,
    const __half* __restrict__ Bh, const __half* __restrict__ Bl,
    const float* __restrict__ bias, float* __restrict__ C,
    int M, int N, int K)
{
  GEMM_BODY(__half, mma_f16)
}

__global__ __launch_bounds__(256, 2) void gemm_bf16(
    const __nv_bfloat16* __restrict__ Ah, const __nv_bfloat16* __restrict__ Al,
    const __nv_bfloat16* __restrict__ Bh, const __nv_bfloat16* __restrict__ Bl,
    const float* __restrict__ bias, float* __restrict__ C,
    int M, int N, int K)
{
  GEMM_BODY(__nv_bfloat16, mma_bf16)
}

// ---------------------------------------------------------------------------
// Normalize q,k + split:
//   qkv[t][3C] -> Qh/Ql, Kh/Kl [h][t][d] fp16; Vbh/Vbl [h][d][t] bf16
// ---------------------------------------------------------------------------
__global__ __launch_bounds__(256) void norm_split(
    const float* __restrict__ qkv,
    __half* __restrict__ Qh, __half* __restrict__ Ql,
    __half* __restrict__ Kh, __half* __restrict__ Kl,
    __nv_bfloat16* __restrict__ Vbh, __nv_bfloat16* __restrict__ Vbl)
{
  __shared__ float Qs[64 * 68];
  __shared__ float Ks[64 * 68];
  __shared__ float invq[64], invk[64];
  const unsigned FULL = 0xffffffffu;
  const int h = blockIdx.y;
  const int t0 = blockIdx.x << 6;
  const int tid = threadIdx.x;

#pragma unroll
  for (int it = 0; it < 4; ++it) {
    int idx = tid + it * 256;
    int r = idx >> 4, c4 = (idx & 15) << 2;
    size_t base = (size_t)(t0 + r) * K3 + h * HD + c4;
    *(float4*)&Qs[r * 68 + c4] = *(const float4*)&qkv[base];
    *(float4*)&Ks[r * 68 + c4] = *(const float4*)&qkv[base + CDIM];
  }
  __syncthreads();

  {
    int row = tid >> 2, seg = tid & 3;
    float sq = 0.f, sk = 0.f;
#pragma unroll
    for (int i = 0; i < 16; ++i) {
      float a = Qs[row * 68 + seg * 16 + i];
      float b = Ks[row * 68 + seg * 16 + i];
      sq = fmaf(a, a, sq);
      sk = fmaf(b, b, sk);
    }
    sq += __shfl_xor_sync(FULL, sq, 1);
    sq += __shfl_xor_sync(FULL, sq, 2);
    sk += __shfl_xor_sync(FULL, sk, 1);
    sk += __shfl_xor_sync(FULL, sk, 2);
    if (seg == 0) {
      invq[row] = 1.0f / fmaxf(sqrtf(sq), 1e-12f);
      invk[row] = 1.0f / fmaxf(sqrtf(sk), 1e-12f);
    }
  }
  __syncthreads();

  {
    int r = tid >> 2, cseg = (tid & 3) << 4;
    float iq = invq[r], ik = invk[r];
    size_t ob = ((size_t)h * T_SEQ + t0 + r) * HD + cseg;
#pragma unroll
    for (int j = 0; j < 4; ++j) {
      float4 qv = *(float4*)&Qs[r * 68 + cseg + 4 * j];
      float4 kv = *(float4*)&Ks[r * 68 + cseg + 4 * j];
      float q0 = qv.x * iq, q1 = qv.y * iq, q2 = qv.z * iq, q3 = qv.w * iq;
      float k0 = kv.x * ik, k1 = kv.y * ik, k2 = kv.z * ik, k3 = kv.w * ik;
      __half2 qh2a(__float2half(q0), __float2half(q1));
      __half2 qh2b(__float2half(q2), __float2half(q3));
      __half2 ql2a(__float2half(q0 - __half2float(qh2a.x)),
                   __float2half(q1 - __half2float(qh2a.y)));
      __half2 ql2b(__float2half(q2 - __half2float(qh2b.x)),
                   __float2half(q3 - __half2float(qh2b.y)));
      __half2 kh2a(__float2half(k0), __float2half(k1));
      __half2 kh2b(__float2half(k2), __float2half(k3));
      __half2 kl2a(__float2half(k0 - __half2float(kh2a.x)),
                   __float2half(k1 - __half2float(kh2a.y)));
      __half2 kl2b(__float2half(k2 - __half2float(kh2b.x)),
                   __float2half(k3 - __half2float(kh2b.y)));
      *(__half2*)&Qh[ob + 4 * j]     = qh2a;
      *(__half2*)&Qh[ob + 4 * j + 2] = qh2b;
      *(__half2*)&Ql[ob + 4 * j]     = ql2a;
      *(__half2*)&Ql[ob + 4 * j + 2] = ql2b;
      *(__half2*)&Kh[ob + 4 * j]     = kh2a;
      *(__half2*)&Kh[ob + 4 * j + 2] = kh2b;
      *(__half2*)&Kl[ob + 4 * j]     = kl2a;
      *(__half2*)&Kl[ob + 4 * j + 2] = kl2b;
    }
  }
  __syncthreads();

  // Stage V, then write transposed bf16 hi/lo [h][d][t]
#pragma unroll
  for (int it = 0; it < 4; ++it) {
    int idx = tid + it * 256;
    int r = idx >> 4, c4 = (idx & 15) << 2;
    size_t base = (size_t)(t0 + r) * K3 + h * HD + 2 * CDIM + c4;
    *(float4*)&Qs[r * 68 + c4] = *(const float4*)&qkv[base];
  }
  __syncthreads();
  {
    int d = tid >> 2, tseg = (tid & 3) << 4;
    size_t vb = ((size_t)h * HD + d) * T_SEQ + t0 + tseg;
#pragma unroll
    for (int j = 0; j < 4; ++j) {
      float v0 = Qs[(tseg + 4 * j + 0) * 68 + d];
      float v1 = Qs[(tseg + 4 * j + 1) * 68 + d];
      float v2 = Qs[(tseg + 4 * j + 2) * 68 + d];
      float v3 = Qs[(tseg + 4 * j + 3) * 68 + d];
      __nv_bfloat162 h01, h23, l01, l23;
      h01.x = __float2bfloat16(v0); l01.x = __float2bfloat16(v0 - __bfloat162float(h01.x));
      h01.y = __float2bfloat16(v1); l01.y = __float2bfloat16(v1 - __bfloat162float(h01.y));
      h23.x = __float2bfloat16(v2); l23.x = __float2bfloat16(v2 - __bfloat162float(h23.x));
      h23.y = __float2bfloat16(v3); l23.y = __float2bfloat16(v3 - __bfloat162float(h23.y));
      *(__nv_bfloat162*)&Vbh[vb + 4 * j]     = h01;
      *(__nv_bfloat162*)&Vbh[vb + 4 * j + 2] = h23;
      *(__nv_bfloat162*)&Vbl[vb + 4 * j]     = l01;
      *(__nv_bfloat162*)&Vbl[vb + 4 * j + 2] = l23;
    }
  }
}

// ---------------------------------------------------------------------------
// Tensorized cumulative linear attention (fp16x3 S-phase).
// Grid (T/128, H), 256 thr (8 warps x 16 q-rows). 32-key tiles, 2-stage
// cp.async, one syncthreads per tile, register-only W repack.
// Phase A: split accumulators (8-way ILP). Phase B: TERM-MAJOR per ng-pair
// (dependent mma spacing 1 -> 4; per-accumulator term order unchanged, so
// results are bitwise identical to R15).
// Stage: Kh/Kl 32x144B fp16, Vh/Vl 64x80B bf16 = 19456B x2.
// ---------------------------------------------------------------------------
#define ATT_STAGE 19456
#define ATT_SMEM  (2 * ATT_STAGE)   // 38912

__global__ __launch_bounds__(256, 2) void attn_mma(
    const __half* __restrict__ Qh_, const __half* __restrict__ Ql_,
    const __half* __restrict__ Kh_, const __half* __restrict__ Kl_,
    const __nv_bfloat16* __restrict__ Vh_, const __nv_bfloat16* __restrict__ Vl_,
    __nv_bfloat16* __restrict__ Yh_, __nv_bfloat16* __restrict__ Yl_)
{
  extern __shared__ char smem[];
  const u32 sb = smem_u32(smem);
  const unsigned FULL = 0xffffffffu;
  const int h = blockIdx.y, q0 = blockIdx.x << 7;
  const int tid = threadIdx.x, lane = tid & 31, w = tid >> 5;
  const int g = lane >> 2, qd = lane & 3;

  // ---- Q fragments (one-time, fp16 m16n8k16 A layout from gmem) ----
  const u32* Qh32 = (const u32*)(Qh_ + ((size_t)h * T_SEQ + q0 + w * 16) * HD);
  const u32* Ql32 = (const u32*)(Ql_ + ((size_t)h * T_SEQ + q0 + w * 16) * HD);
  u32 qfh[4][4], qfl[4][4];
#pragma unroll
  for (int kc = 0; kc < 4; ++kc) {
    int c0 = kc * 8 + qd;
    qfh[kc][0] = Qh32[g * 32 + c0];       qfh[kc][1] = Qh32[(g + 8) * 32 + c0];
    qfh[kc][2] = Qh32[g * 32 + c0 + 4];   qfh[kc][3] = Qh32[(g + 8) * 32 + c0 + 4];
    qfl[kc][0] = Ql32[g * 32 + c0];       qfl[kc][1] = Ql32[(g + 8) * 32 + c0];
    qfl[kc][2] = Ql32[g * 32 + c0 + 4];   qfl[kc][3] = Ql32[(g + 8) * 32 + c0 + 4];
  }

  // 256-thread stage loader: K 512 chunks + V 512 chunks, 4 per thread
  auto load_stage = [&](int st, int k0) {
    u32 base = sb + st * ATT_STAGE;
#pragma unroll
    for (int i = 0; i < 2; ++i) {
      int idx = tid + (i << 8);            // 0..511
      int ten = idx >> 8, u = idx & 255;   // 32 rows x 8 x 16B per tensor
      int row = u >> 3, q8 = u & 7;
      const __half* src = (ten ? Kl_ : Kh_) +
          ((size_t)h * T_SEQ + k0 + row) * HD + q8 * 8;
      cpasync16(base + ten * 4608 + row * 144 + q8 * 16, src);
    }
#pragma unroll
    for (int i = 0; i < 2; ++i) {
      int idx = tid + (i << 8);            // 0..511
      int ten = idx >> 8, u = idx & 255;   // 64 rows x 4 x 16B per tensor
      int row = u >> 2, q4 = u & 3;
      const __nv_bfloat16* src = (ten ? Vl_ : Vh_) +
          ((size_t)h * HD + row) * T_SEQ + k0 + q4 * 8;
      cpasync16(base + 9216 + ten * 5120 + row * 80 + q4 * 16, src);
    }
    CP_COMMIT();
  };

  // lane-dependent ldmatrix offsets
  const u32 k_lane = (u32)(((lane & 7) + ((lane >> 4) << 3)) * 144
                           + ((lane >> 3) & 1) * 16);
  const u32 v_lane = (u32)(((lane & 7) + ((lane >> 4) & 1) * 8) * 80
                           + ((lane >> 3) & 1) * 16);

  float Yacc[8][4] = {};
  float carry0 = 0.f, carry1 = 0.f;

  load_stage(0, 0);

  for (int c = 0; c < T_SEQ / 32; ++c) {
    asm volatile("cp.async.wait_group 0;" ::: "memory");
    __syncthreads();
    if (c + 1 < T_SEQ / 32) load_stage((c + 1) & 1, (c + 1) * 32);

    const u32 st = sb + (c & 1) * ATT_STAGE;

    // ---- Phase A: S = Q K^T (fp16x3, split accumulators, 8-way ILP) ----
    float Sa[4][4] = {};   // Qh*Kh
    float Sb[4][4] = {};   // Qh*Kl + Ql*Kh
#pragma unroll
    for (int kc = 0; kc < 4; ++kc) {
      u32 kh0[4], kh1[4], kl0[4], kl1[4];
      u32 ka = st + kc * 32 + k_lane;
      LDSM4(kh0, ka);                       // keys 0-15
      LDSM4(kh1, ka + 16 * 144);            // keys 16-31
      LDSM4(kl0, ka + 4608);
      LDSM4(kl1, ka + 4608 + 16 * 144);
      mma_f16(Sa[0], qfh[kc], kh0[0], kh0[1]);
      mma_f16(Sa[1], qfh[kc], kh0[2], kh0[3]);
      mma_f16(Sa[2], qfh[kc], kh1[0], kh1[1]);
      mma_f16(Sa[3], qfh[kc], kh1[2], kh1[3]);
      mma_f16(Sb[0], qfh[kc], kl0[0], kl0[1]);
      mma_f16(Sb[1], qfh[kc], kl0[2], kl0[3]);
      mma_f16(Sb[2], qfh[kc], kl1[0], kl1[1]);
      mma_f16(Sb[3], qfh[kc], kl1[2], kl1[3]);
      mma_f16(Sb[0], qfl[kc], kh0[0], kh0[1]);
      mma_f16(Sb[1], qfl[kc], kh0[2], kh0[3]);
      mma_f16(Sb[2], qfl[kc], kh1[0], kh1[1]);
      mma_f16(Sb[3], qfl[kc], kh1[2], kh1[3]);
    }
#pragma unroll
    for (int i = 0; i < 4; ++i)
#pragma unroll
      for (int e = 0; e < 4; ++e) Sa[i][e] += Sb[i][e];

    // ---- Scan on fragments: independent quad scans + prefix combine.
    //      W packed DIRECTLY into Phase-B A-fragments (C-frag == A-frag). ----
    u32 Wh[2][4], Wl[2][4];
#pragma unroll
    for (int half = 0; half < 2; ++half) {
      float bb = half ? carry1 : carry0;
      float run[4], tot[4];
#pragma unroll
      for (int nf = 0; nf < 4; ++nf) {
        float s0 = Sa[nf][half * 2], s1 = Sa[nf][half * 2 + 1];
        float r = s0 + s1;
        float n1 = __shfl_up_sync(FULL, r, 1, 4); if (qd >= 1) r += n1;
        float n2 = __shfl_up_sync(FULL, r, 2, 4); if (qd >= 2) r += n2;
        run[nf] = r;
        tot[nf] = __shfl_sync(FULL, r, 3, 4);
      }
      float base[4];
      base[0] = bb;
      base[1] = base[0] + tot[0];
      base[2] = base[1] + tot[1];
      base[3] = base[2] + tot[2];
      bb = base[3] + tot[3];
#pragma unroll
      for (int nf = 0; nf < 4; ++nf) {
        float s1 = Sa[nf][half * 2 + 1];
        float s0 = Sa[nf][half * 2];
        float cum1 = base[nf] + run[nf];
        float cum0 = cum1 - s1;
        float w0 = __fdividef(s0, fmaxf(cum0, 1e-6f));
        float w1 = __fdividef(s1, fmaxf(cum1, 1e-6f));
        u32 hw = packbf2(w0, w1);
        __nv_bfloat162 hv = *(__nv_bfloat162*)&hw;
        u32 lw = packbf2(w0 - __bfloat162float(hv.x),
                         w1 - __bfloat162float(hv.y));
        Wh[nf >> 1][((nf & 1) << 1) | half] = hw;
        Wl[nf >> 1][((nf & 1) << 1) | half] = lw;
      }
      if (half) carry1 = bb; else carry0 = bb;
    }

    // ---- Phase B: Y += W @ V (bf16x3, TERM-MAJOR per ng-pair) ----
    // Per Yacc[nf] the term order stays h.h, h.l, l.h -> bitwise identical.
    const u32 vst = st + 9216;
#pragma unroll
    for (int ks = 0; ks < 2; ++ks) {
#pragma unroll
      for (int np = 0; np < 2; ++np) {      // ng pair: (2np, 2np+1)
        u32 vh0[4], vl0[4], vh1[4], vl1[4];
        u32 va0 = vst + (2 * np) * 1280 + v_lane + ks * 32;
        u32 va1 = vst + (2 * np + 1) * 1280 + v_lane + ks * 32;
        LDSM4(vh0, va0);
        LDSM4(vl0, va0 + 5120);
        LDSM4(vh1, va1);
        LDSM4(vl1, va1 + 5120);
        float* y0 = Yacc[4 * np + 0];
        float* y1 = Yacc[4 * np + 1];
        float* y2 = Yacc[4 * np + 2];
        float* y3 = Yacc[4 * np + 3];
        // term h.h (4 independent)
        mma_bf16(y0, Wh[ks], vh0[0], vh0[1]);
        mma_bf16(y1, Wh[ks], vh0[2], vh0[3]);
        mma_bf16(y2, Wh[ks], vh1[0], vh1[1]);
        mma_bf16(y3, Wh[ks], vh1[2], vh1[3]);
        // term h.l (4 independent)
        mma_bf16(y0, Wh[ks], vl0[0], vl0[1]);
        mma_bf16(y1, Wh[ks], vl0[2], vl0[3]);
        mma_bf16(y2, Wh[ks], vl1[0], vl1[1]);
        mma_bf16(y3, Wh[ks], vl1[2], vl1[3]);
        // term l.h (4 independent)
        mma_bf16(y0, Wl[ks], vh0[0], vh0[1]);
        mma_bf16(y1, Wl[ks], vh0[2], vh0[3]);
        mma_bf16(y2, Wl[ks], vh1[0], vh1[1]);
        mma_bf16(y3, Wl[ks], vh1[2], vh1[3]);
      }
    }
  }

  // ---- Epilogue: split Y to bf16 hi/lo, store [t][C] ----
  const int row0 = q0 + w * 16 + g;
  const int colb = h * HD + 2 * qd;
#pragma unroll
  for (int nf = 0; nf < 8; ++nf) {
    int col = colb + nf * 8;
    size_t o0 = (size_t)row0 * CDIM + col;
    size_t o1 = (size_t)(row0 + 8) * CDIM + col;
    __nv_bfloat162 h2, l2;
    h2.x = __float2bfloat16(Yacc[nf][0]);
    l2.x = __float2bfloat16(Yacc[nf][0] - __bfloat162float(h2.x));
    h2.y = __float2bfloat16(Yacc[nf][1]);
    l2.y = __float2bfloat16(Yacc[nf][1] - __bfloat162float(h2.y));
    *(__nv_bfloat162*)&Yh_[o0] = h2;
    *(__nv_bfloat162*)&Yl_[o0] = l2;
    h2.x = __float2bfloat16(Yacc[nf][2]);
    l2.x = __float2bfloat16(Yacc[nf][2] - __bfloat162float(h2.x));
    h2.y = __float2bfloat16(Yacc[nf][3]);
    l2.y = __float2bfloat16(Yacc[nf][3] - __bfloat162float(h2.y));
    *(__nv_bfloat162*)&Yh_[o1] = h2;
    *(__nv_bfloat162*)&Yl_[o1] = l2;
  }
}

// ---------------------------------------------------------------------------
extern "C" void kernel_launch(void* const* d_in, const int* in_sizes, int n_in,
                              void* d_out, int out_size)
{
  const float* x      = (const float*)d_in[0];
  const float* w_attn = (const float*)d_in[1];
  const float* b_attn = (const float*)d_in[2];
  const float* w_proj = (const float*)d_in[3];
  const float* b_proj = (const float*)d_in[4];
  float* out = (float*)d_out;

  float* qkv;
  __half *xh, *xl, *wah, *wal, *qh, *ql, *kh, *kl;
  __nv_bfloat16 *wph, *wpl, *vbh, *vbl, *yh, *yl;
  cudaGetSymbolAddress((void**)&qkv, g_qkv);
  cudaGetSymbolAddress((void**)&xh,  g_xh);
  cudaGetSymbolAddress((void**)&xl,  g_xl);
  cudaGetSymbolAddress((void**)&wah, g_wah);
  cudaGetSymbolAddress((void**)&wal, g_wal);
  cudaGetSymbolAddress((void**)&wph, g_wph);
  cudaGetSymbolAddress((void**)&wpl, g_wpl);
  cudaGetSymbolAddress((void**)&qh,  g_qh);
  cudaGetSymbolAddress((void**)&ql,  g_ql);
  cudaGetSymbolAddress((void**)&kh,  g_kh);
  cudaGetSymbolAddress((void**)&kl,  g_kl);
  cudaGetSymbolAddress((void**)&vbh, g_vbh);
  cudaGetSymbolAddress((void**)&vbl, g_vbl);
  cudaGetSymbolAddress((void**)&yh,  g_yh);
  cudaGetSymbolAddress((void**)&yl,  g_yl);

  cudaFuncSetAttribute(gemm_f16,
                       cudaFuncAttributeMaxDynamicSharedMemorySize, GEMM_SMEM);
  cudaFuncSetAttribute(gemm_bf16,
                       cudaFuncAttributeMaxDynamicSharedMemorySize, GEMM_SMEM);
  cudaFuncSetAttribute(attn_mma,
                       cudaFuncAttributeMaxDynamicSharedMemorySize, ATT_SMEM);

  const int n4 = T_SEQ * CDIM / 4;

  // 0) conversions
  split_f16<<<(n4 + 255) / 256, 256>>>(x, xh, xl, n4);
  transpose_split_f16<<<dim3(K3 / 32, CDIM / 32), dim3(32, 8)>>>(
      w_attn, wah, wal, CDIM, K3);
  transpose_split_bf16<<<dim3(CDIM / 32, CDIM / 32), dim3(32, 8)>>>(
      w_proj, wph, wpl, CDIM, CDIM);

  // 1) qkv = x @ w_attn + b_attn   (fp16x3, term-major, 2 CTAs/SM)
  gemm_f16<<<dim3(K3 / 128, T_SEQ / 128), 256, GEMM_SMEM>>>(
      xh, xl, wah, wal, b_attn, qkv, T_SEQ, K3, CDIM);

  // 2) normalize + split q,k (fp16) and v (bf16, transposed)
  norm_split<<<dim3(T_SEQ / 64, NHEAD), 256>>>(qkv, qh, ql, kh, kl, vbh, vbl);

  // 3) tensorized cumulative linear attention -> yh/yl bf16
  attn_mma<<<dim3(T_SEQ / 128, NHEAD), 256, ATT_SMEM>>>(
      qh, ql, kh, kl, vbh, vbl, yh, yl);

  // 4) out = y @ w_proj + b_proj  (bf16x3, term-major, 2 CTAs/SM)
  gemm_bf16<<<dim3(CDIM / 128, T_SEQ / 128), 256, GEMM_SMEM>>>(
      yh, yl, wph, wpl, b_proj, out, T_SEQ, CDIM, CDIM);
}

// round 17
// speedup vs baseline: 1.0047x; 1.0047x over previous
#include <cuda_runtime.h>
#include <cuda_bf16.h>
#include <cuda_fp16.h>
#include <cstdint>

#define T_SEQ 4096
#define NHEAD 12
#define HD    64
#define CDIM  768
#define K3    (3*CDIM)

typedef unsigned int u32;

// ---- base-target helpers (sm_80+ PTX, no 'a' suffix) ----------------------
__device__ __forceinline__ u32 smem_u32(const void* p) {
  u32 a;
  asm("{ .reg .u64 t; cvta.to.shared.u64 t, %1; cvt.u32.u64 %0, t; }"
      : "=r"(a) : "l"(p));
  return a;
}
__device__ __forceinline__ void cpasync16(u32 dst, const void* src) {
  asm volatile("cp.async.ca.shared.global [%0], [%1], 16;"
               :: "r"(dst), "l"(src) : "memory");
}
#define CP_COMMIT() asm volatile("cp.async.commit_group;" ::: "memory")
#define LDSM4(R, addr)                                                        \
  asm volatile("ldmatrix.sync.aligned.m8n8.x4.shared.b16 {%0,%1,%2,%3}, [%4];"\
               : "=r"((R)[0]), "=r"((R)[1]), "=r"((R)[2]), "=r"((R)[3])       \
               : "r"(addr))
__device__ __forceinline__ void mma_bf16(float* c, const u32* a, u32 b0, u32 b1) {
  asm volatile(
      "mma.sync.aligned.m16n8k16.row.col.f32.bf16.bf16.f32 "
      "{%0,%1,%2,%3}, {%4,%5,%6,%7}, {%8,%9}, {%0,%1,%2,%3};"
      : "+f"(c[0]), "+f"(c[1]), "+f"(c[2]), "+f"(c[3])
      : "r"(a[0]), "r"(a[1]), "r"(a[2]), "r"(a[3]), "r"(b0), "r"(b1));
}
__device__ __forceinline__ void mma_f16(float* c, const u32* a, u32 b0, u32 b1) {
  asm volatile(
      "mma.sync.aligned.m16n8k16.row.col.f32.f16.f16.f32 "
      "{%0,%1,%2,%3}, {%4,%5,%6,%7}, {%8,%9}, {%0,%1,%2,%3};"
      : "+f"(c[0]), "+f"(c[1]), "+f"(c[2]), "+f"(c[3])
      : "r"(a[0]), "r"(a[1]), "r"(a[2]), "r"(a[3]), "r"(b0), "r"(b1));
}
// pack two fp32 into bf16x2 register (lo = first arg)
__device__ __forceinline__ u32 packbf2(float lo, float hi) {
  u32 r;
  asm("cvt.rn.bf16x2.f32 %0, %1, %2;" : "=r"(r) : "f"(hi), "f"(lo));
  return r;
}

// ---- scratch --------------------------------------------------------------
__device__ float g_qkv[T_SEQ * K3];
__device__ __half g_xh[T_SEQ * CDIM], g_xl[T_SEQ * CDIM];
__device__ __half g_wah[K3 * CDIM],  g_wal[K3 * CDIM];            // [N][K] fp16
__device__ __nv_bfloat16 g_wph[CDIM * CDIM], g_wpl[CDIM * CDIM];  // [N][K] bf16
__device__ __half g_qh[NHEAD * T_SEQ * HD], g_ql[NHEAD * T_SEQ * HD];  // [h][t][d]
__device__ __half g_kh[NHEAD * T_SEQ * HD], g_kl[NHEAD * T_SEQ * HD];  // [h][t][d]
__device__ __nv_bfloat16 g_vbh[NHEAD * HD * T_SEQ], g_vbl[NHEAD * HD * T_SEQ]; // [h][d][t]
__device__ __nv_bfloat16 g_yh[T_SEQ * CDIM], g_yl[T_SEQ * CDIM];

// ---------------------------------------------------------------------------
// split fp32 -> (hi, lo) fp16
// ---------------------------------------------------------------------------
__global__ __launch_bounds__(256) void split_f16(
    const float* __restrict__ in, __half* __restrict__ oh,
    __half* __restrict__ ol, int n4)
{
  int i = blockIdx.x * 256 + threadIdx.x;
  if (i >= n4) return;
  float4 v = ((const float4*)in)[i];
  __half h0 = __float2half(v.x), h1 = __float2half(v.y);
  __half h2 = __float2half(v.z), h3 = __float2half(v.w);
  __half l0 = __float2half(v.x - __half2float(h0));
  __half l1 = __float2half(v.y - __half2float(h1));
  __half l2 = __float2half(v.z - __half2float(h2));
  __half l3 = __float2half(v.w - __half2float(h3));
  ((__half2*)oh)[2 * i + 0] = __half2(h0, h1);
  ((__half2*)oh)[2 * i + 1] = __half2(h2, h3);
  ((__half2*)ol)[2 * i + 0] = __half2(l0, l1);
  ((__half2*)ol)[2 * i + 1] = __half2(l2, l3);
}

// ---------------------------------------------------------------------------
// transpose + split fp16: w[K][N] -> out[N][K] (hi, lo)
// ---------------------------------------------------------------------------
__global__ __launch_bounds__(256) void transpose_split_f16(
    const float* __restrict__ w, __half* __restrict__ oh,
    __half* __restrict__ ol, int K, int N)
{
  __shared__ float t[32][33];
  int n0 = blockIdx.x * 32, k0 = blockIdx.y * 32;
  int tx = threadIdx.x, ty = threadIdx.y;
#pragma unroll
  for (int i = ty; i < 32; i += 8)
    t[i][tx] = w[(size_t)(k0 + i) * N + n0 + tx];
  __syncthreads();
#pragma unroll
  for (int i = ty; i < 32; i += 8) {
    float v = t[tx][i];
    __half h = __float2half(v);
    __half l = __float2half(v - __half2float(h));
    oh[(size_t)(n0 + i) * K + k0 + tx] = h;
    ol[(size_t)(n0 + i) * K + k0 + tx] = l;
  }
}

// ---------------------------------------------------------------------------
// transpose + split bf16: w[K][N] -> out[N][K] (hi, lo) bf16
// ---------------------------------------------------------------------------
__global__ __launch_bounds__(256) void transpose_split_bf16(
    const float* __restrict__ w, __nv_bfloat16* __restrict__ oh,
    __nv_bfloat16* __restrict__ ol, int K, int N)
{
  __shared__ float t[32][33];
  int n0 = blockIdx.x * 32, k0 = blockIdx.y * 32;
  int tx = threadIdx.x, ty = threadIdx.y;
#pragma unroll
  for (int i = ty; i < 32; i += 8)
    t[i][tx] = w[(size_t)(k0 + i) * N + n0 + tx];
  __syncthreads();
#pragma unroll
  for (int i = ty; i < 32; i += 8) {
    float v = t[tx][i];
    __nv_bfloat16 h = __float2bfloat16(v);
    __nv_bfloat16 l = __float2bfloat16(v - __bfloat162float(h));
    oh[(size_t)(n0 + i) * K + k0 + tx] = h;
    ol[(size_t)(n0 + i) * K + k0 + tx] = l;
  }
}

// ---------------------------------------------------------------------------
// 16-bit 3-term GEMM: 2-stage cp.async, TERM-MAJOR mma ordering, 2 CTAs/SM.
// CTA 128x128, 8 warps (32x64), BK=32, 80B rows.
// ---------------------------------------------------------------------------
#define GSTAGE 40960
#define GEMM_SMEM (2 * GSTAGE)

#define GEMM_BODY(T16, MMA)                                                   \
  extern __shared__ char smem[];                                              \
  const u32 sb = smem_u32(smem);                                              \
  const int tid = threadIdx.x, lane = tid & 31, wid = tid >> 5;               \
  const int m0 = blockIdx.y << 7, n0 = blockIdx.x << 7;                       \
  const int wm = wid >> 1, wn = wid & 1;                                      \
  const T16* srcs[4] = {Ah, Al, Bh, Bl};                                      \
  float acc[2][8][4] = {};                                                    \
  const int nchunks = K >> 5;                                                 \
  auto load_stage = [&](int st, int k0) {                                     \
    u32 base = sb + st * GSTAGE;                                              \
    _Pragma("unroll")                                                         \
    for (int i = 0; i < 8; ++i) {                                             \
      int idx = tid + (i << 8);                                               \
      int ten = idx >> 9, u = idx & 511;                                      \
      int row = u >> 2, q = u & 3;                                            \
      int gr = (ten < 2 ? m0 : n0) + row;                                     \
      cpasync16(base + ten * 10240 + row * 80 + q * 16,                       \
                &srcs[ten][(size_t)gr * K + k0 + q * 8]);                     \
    }                                                                         \
    CP_COMMIT();                                                              \
  };                                                                          \
  load_stage(0, 0);                                                           \
  for (int c = 0; c < nchunks; ++c) {                                         \
    const bool pf = (c + 1 < nchunks);                                        \
    if (pf) load_stage((c + 1) & 1, (c + 1) << 5);                            \
    if (pf) asm volatile("cp.async.wait_group 1;" ::: "memory");              \
    else    asm volatile("cp.async.wait_group 0;" ::: "memory");              \
    __syncthreads();                                                          \
    const u32 base = sb + (c & 1) * GSTAGE;                                   \
    const u32 aA = base, aAl = base + 10240, aB = base + 20480,               \
              aBl = base + 30720;                                             \
    _Pragma("unroll")                                                         \
    for (int ks = 0; ks < 32; ks += 16) {                                     \
      const int arow = lane & 15, asel = lane >> 4;                           \
      u32 ah[2][4], al[2][4];                                                 \
      _Pragma("unroll")                                                       \
      for (int mt = 0; mt < 2; ++mt) {                                        \
        u32 off = (u32)((wm * 32 + mt * 16 + arow) * 80 +                     \
                        (ks + asel * 8) * 2);                                 \
        LDSM4(ah[mt], aA + off);                                              \
        LDSM4(al[mt], aAl + off);                                             \
      }                                                                       \
      const int nrow = (lane & 7) + ((lane >> 4) << 3);                       \
      const int koff = ks + (((lane >> 3) & 1) << 3);                         \
      u32 bh[4][4], bl[4][4];                                                 \
      _Pragma("unroll")                                                       \
      for (int ng = 0; ng < 4; ++ng) {                                        \
        u32 off = (u32)((wn * 64 + ng * 16 + nrow) * 80 + koff * 2);          \
        LDSM4(bh[ng], aB + off);                                              \
        LDSM4(bl[ng], aBl + off);                                             \
      }                                                                       \
      /* term-major: all h.h, then all h.l, then all l.h (per-acc order kept) */ \
      _Pragma("unroll")                                                       \
      for (int mt = 0; mt < 2; ++mt)                                          \
        _Pragma("unroll")                                                     \
        for (int nt = 0; nt < 8; ++nt) {                                      \
          const int ng = nt >> 1, sel = (nt & 1) << 1;                        \
          MMA(acc[mt][nt], ah[mt], bh[ng][sel], bh[ng][sel + 1]);             \
        }                                                                     \
      _Pragma("unroll")                                                       \
      for (int mt = 0; mt < 2; ++mt)                                          \
        _Pragma("unroll")                                                     \
        for (int nt = 0; nt < 8; ++nt) {                                      \
          const int ng = nt >> 1, sel = (nt & 1) << 1;                        \
          MMA(acc[mt][nt], ah[mt], bl[ng][sel], bl[ng][sel + 1]);             \
        }                                                                     \
      _Pragma("unroll")                                                       \
      for (int mt = 0; mt < 2; ++mt)                                          \
        _Pragma("unroll")                                                     \
        for (int nt = 0; nt < 8; ++nt) {                                      \
          const int ng = nt >> 1, sel = (nt & 1) << 1;                        \
          MMA(acc[mt][nt], al[mt], bh[ng][sel], bh[ng][sel + 1]);             \
        }                                                                     \
    }                                                                         \
    __syncthreads();                                                          \
  }                                                                           \
  const int rbase = m0 + wm * 32 + (lane >> 2);                               \
  const int cbase = n0 + wn * 64 + ((lane & 3) << 1);                         \
  _Pragma("unroll")                                                           \
  for (int mt = 0; mt < 2; ++mt)                                              \
    _Pragma("unroll")                                                         \
    for (int nt = 0; nt < 8; ++nt) {                                          \
      int row = rbase + mt * 16;                                              \
      int col = cbase + nt * 8;                                               \
      float b0 = bias[col], b1 = bias[col + 1];                               \
      *(float2*)&C[(size_t)row * N + col] =                                   \
          make_float2(acc[mt][nt][0] + b0, acc[mt][nt][1] + b1);              \
      *(float2*)&C[(size_t)(row + 8) * N + col] =                             \
          make_float2(acc[mt][nt][2] + b0, acc[mt][nt][3] + b1);              \
    }

__global__ __launch_bounds__(256, 2) void gemm_f16(
    const __half* __restrict__ Ah, const __half* __restrict__ Al,
    const __half* __restrict__ Bh, const __half* __restrict__ Bl,
    const float* __restrict__ bias, float* __restrict__ C,
    int M, int N, int K)
{
  GEMM_BODY(__half, mma_f16)
}

__global__ __launch_bounds__(256, 2) void gemm_bf16(
    const __nv_bfloat16* __restrict__ Ah, const __nv_bfloat16* __restrict__ Al,
    const __nv_bfloat16* __restrict__ Bh, const __nv_bfloat16* __restrict__ Bl,
    const float* __restrict__ bias, float* __restrict__ C,
    int M, int N, int K)
{
  GEMM_BODY(__nv_bfloat16, mma_bf16)
}

// ---------------------------------------------------------------------------
// Normalize q,k + split:
//   qkv[t][3C] -> Qh/Ql, Kh/Kl [h][t][d] fp16; Vbh/Vbl [h][d][t] bf16
// ---------------------------------------------------------------------------
__global__ __launch_bounds__(256) void norm_split(
    const float* __restrict__ qkv,
    __half* __restrict__ Qh, __half* __restrict__ Ql,
    __half* __restrict__ Kh, __half* __restrict__ Kl,
    __nv_bfloat16* __restrict__ Vbh, __nv_bfloat16* __restrict__ Vbl)
{
  __shared__ float Qs[64 * 68];
  __shared__ float Ks[64 * 68];
  __shared__ float invq[64], invk[64];
  const unsigned FULL = 0xffffffffu;
  const int h = blockIdx.y;
  const int t0 = blockIdx.x << 6;
  const int tid = threadIdx.x;

#pragma unroll
  for (int it = 0; it < 4; ++it) {
    int idx = tid + it * 256;
    int r = idx >> 4, c4 = (idx & 15) << 2;
    size_t base = (size_t)(t0 + r) * K3 + h * HD + c4;
    *(float4*)&Qs[r * 68 + c4] = *(const float4*)&qkv[base];
    *(float4*)&Ks[r * 68 + c4] = *(const float4*)&qkv[base + CDIM];
  }
  __syncthreads();

  {
    int row = tid >> 2, seg = tid & 3;
    float sq = 0.f, sk = 0.f;
#pragma unroll
    for (int i = 0; i < 16; ++i) {
      float a = Qs[row * 68 + seg * 16 + i];
      float b = Ks[row * 68 + seg * 16 + i];
      sq = fmaf(a, a, sq);
      sk = fmaf(b, b, sk);
    }
    sq += __shfl_xor_sync(FULL, sq, 1);
    sq += __shfl_xor_sync(FULL, sq, 2);
    sk += __shfl_xor_sync(FULL, sk, 1);
    sk += __shfl_xor_sync(FULL, sk, 2);
    if (seg == 0) {
      invq[row] = 1.0f / fmaxf(sqrtf(sq), 1e-12f);
      invk[row] = 1.0f / fmaxf(sqrtf(sk), 1e-12f);
    }
  }
  __syncthreads();

  {
    int r = tid >> 2, cseg = (tid & 3) << 4;
    float iq = invq[r], ik = invk[r];
    size_t ob = ((size_t)h * T_SEQ + t0 + r) * HD + cseg;
#pragma unroll
    for (int j = 0; j < 4; ++j) {
      float4 qv = *(float4*)&Qs[r * 68 + cseg + 4 * j];
      float4 kv = *(float4*)&Ks[r * 68 + cseg + 4 * j];
      float q0 = qv.x * iq, q1 = qv.y * iq, q2 = qv.z * iq, q3 = qv.w * iq;
      float k0 = kv.x * ik, k1 = kv.y * ik, k2 = kv.z * ik, k3 = kv.w * ik;
      __half2 qh2a(__float2half(q0), __float2half(q1));
      __half2 qh2b(__float2half(q2), __float2half(q3));
      __half2 ql2a(__float2half(q0 - __half2float(qh2a.x)),
                   __float2half(q1 - __half2float(qh2a.y)));
      __half2 ql2b(__float2half(q2 - __half2float(qh2b.x)),
                   __float2half(q3 - __half2float(qh2b.y)));
      __half2 kh2a(__float2half(k0), __float2half(k1));
      __half2 kh2b(__float2half(k2), __float2half(k3));
      __half2 kl2a(__float2half(k0 - __half2float(kh2a.x)),
                   __float2half(k1 - __half2float(kh2a.y)));
      __half2 kl2b(__float2half(k2 - __half2float(kh2b.x)),
                   __float2half(k3 - __half2float(kh2b.y)));
      *(__half2*)&Qh[ob + 4 * j]     = qh2a;
      *(__half2*)&Qh[ob + 4 * j + 2] = qh2b;
      *(__half2*)&Ql[ob + 4 * j]     = ql2a;
      *(__half2*)&Ql[ob + 4 * j + 2] = ql2b;
      *(__half2*)&Kh[ob + 4 * j]     = kh2a;
      *(__half2*)&Kh[ob + 4 * j + 2] = kh2b;
      *(__half2*)&Kl[ob + 4 * j]     = kl2a;
      *(__half2*)&Kl[ob + 4 * j + 2] = kl2b;
    }
  }
  __syncthreads();

  // Stage V, then write transposed bf16 hi/lo [h][d][t]
#pragma unroll
  for (int it = 0; it < 4; ++it) {
    int idx = tid + it * 256;
    int r = idx >> 4, c4 = (idx & 15) << 2;
    size_t base = (size_t)(t0 + r) * K3 + h * HD + 2 * CDIM + c4;
    *(float4*)&Qs[r * 68 + c4] = *(const float4*)&qkv[base];
  }
  __syncthreads();
  {
    int d = tid >> 2, tseg = (tid & 3) << 4;
    size_t vb = ((size_t)h * HD + d) * T_SEQ + t0 + tseg;
#pragma unroll
    for (int j = 0; j < 4; ++j) {
      float v0 = Qs[(tseg + 4 * j + 0) * 68 + d];
      float v1 = Qs[(tseg + 4 * j + 1) * 68 + d];
      float v2 = Qs[(tseg + 4 * j + 2) * 68 + d];
      float v3 = Qs[(tseg + 4 * j + 3) * 68 + d];
      __nv_bfloat162 h01, h23, l01, l23;
      h01.x = __float2bfloat16(v0); l01.x = __float2bfloat16(v0 - __bfloat162float(h01.x));
      h01.y = __float2bfloat16(v1); l01.y = __float2bfloat16(v1 - __bfloat162float(h01.y));
      h23.x = __float2bfloat16(v2); l23.x = __float2bfloat16(v2 - __bfloat162float(h23.x));
      h23.y = __float2bfloat16(v3); l23.y = __float2bfloat16(v3 - __bfloat162float(h23.y));
      *(__nv_bfloat162*)&Vbh[vb + 4 * j]     = h01;
      *(__nv_bfloat162*)&Vbh[vb + 4 * j + 2] = h23;
      *(__nv_bfloat162*)&Vbl[vb + 4 * j]     = l01;
      *(__nv_bfloat162*)&Vbl[vb + 4 * j + 2] = l23;
    }
  }
}

// ---------------------------------------------------------------------------
// Tensorized cumulative linear attention (fp16x3 S-phase).
// Grid (T/128, H), 256 thr (8 warps x 16 q-rows). 32-key tiles, 2-stage
// cp.async, one syncthreads per tile, register-only W repack.
// Phase A: split accumulators (8-way ILP). Phase B: TERM-MAJOR per ng-pair.
// Stage: Kh/Kl 32x144B fp16, Vh/Vl 64x80B bf16 = 19456B x2.
// ---------------------------------------------------------------------------
#define ATT_STAGE 19456
#define ATT_SMEM  (2 * ATT_STAGE)   // 38912

__global__ __launch_bounds__(256, 2) void attn_mma(
    const __half* __restrict__ Qh_, const __half* __restrict__ Ql_,
    const __half* __restrict__ Kh_, const __half* __restrict__ Kl_,
    const __nv_bfloat16* __restrict__ Vh_, const __nv_bfloat16* __restrict__ Vl_,
    __nv_bfloat16* __restrict__ Yh_, __nv_bfloat16* __restrict__ Yl_)
{
  extern __shared__ char smem[];
  const u32 sb = smem_u32(smem);
  const unsigned FULL = 0xffffffffu;
  const int h = blockIdx.y, q0 = blockIdx.x << 7;
  const int tid = threadIdx.x, lane = tid & 31, w = tid >> 5;
  const int g = lane >> 2, qd = lane & 3;

  // ---- Q fragments (one-time, fp16 m16n8k16 A layout from gmem) ----
  const u32* Qh32 = (const u32*)(Qh_ + ((size_t)h * T_SEQ + q0 + w * 16) * HD);
  const u32* Ql32 = (const u32*)(Ql_ + ((size_t)h * T_SEQ + q0 + w * 16) * HD);
  u32 qfh[4][4], qfl[4][4];
#pragma unroll
  for (int kc = 0; kc < 4; ++kc) {
    int c0 = kc * 8 + qd;
    qfh[kc][0] = Qh32[g * 32 + c0];       qfh[kc][1] = Qh32[(g + 8) * 32 + c0];
    qfh[kc][2] = Qh32[g * 32 + c0 + 4];   qfh[kc][3] = Qh32[(g + 8) * 32 + c0 + 4];
    qfl[kc][0] = Ql32[g * 32 + c0];       qfl[kc][1] = Ql32[(g + 8) * 32 + c0];
    qfl[kc][2] = Ql32[g * 32 + c0 + 4];   qfl[kc][3] = Ql32[(g + 8) * 32 + c0 + 4];
  }

  // 256-thread stage loader: K 512 chunks + V 512 chunks, 4 per thread
  auto load_stage = [&](int st, int k0) {
    u32 base = sb + st * ATT_STAGE;
#pragma unroll
    for (int i = 0; i < 2; ++i) {
      int idx = tid + (i << 8);            // 0..511
      int ten = idx >> 8, u = idx & 255;   // 32 rows x 8 x 16B per tensor
      int row = u >> 3, q8 = u & 7;
      const __half* src = (ten ? Kl_ : Kh_) +
          ((size_t)h * T_SEQ + k0 + row) * HD + q8 * 8;
      cpasync16(base + ten * 4608 + row * 144 + q8 * 16, src);
    }
#pragma unroll
    for (int i = 0; i < 2; ++i) {
      int idx = tid + (i << 8);            // 0..511
      int ten = idx >> 8, u = idx & 255;   // 64 rows x 4 x 16B per tensor
      int row = u >> 2, q4 = u & 3;
      const __nv_bfloat16* src = (ten ? Vl_ : Vh_) +
          ((size_t)h * HD + row) * T_SEQ + k0 + q4 * 8;
      cpasync16(base + 9216 + ten * 5120 + row * 80 + q4 * 16, src);
    }
    CP_COMMIT();
  };

  // lane-dependent ldmatrix offsets
  const u32 k_lane = (u32)(((lane & 7) + ((lane >> 4) << 3)) * 144
                           + ((lane >> 3) & 1) * 16);
  const u32 v_lane = (u32)(((lane & 7) + ((lane >> 4) & 1) * 8) * 80
                           + ((lane >> 3) & 1) * 16);

  float Yacc[8][4] = {};
  float carry0 = 0.f, carry1 = 0.f;

  load_stage(0, 0);

  for (int c = 0; c < T_SEQ / 32; ++c) {
    asm volatile("cp.async.wait_group 0;" ::: "memory");
    __syncthreads();
    if (c + 1 < T_SEQ / 32) load_stage((c + 1) & 1, (c + 1) * 32);

    const u32 st = sb + (c & 1) * ATT_STAGE;

    // ---- Phase A: S = Q K^T (fp16x3, split accumulators, 8-way ILP) ----
    float Sa[4][4] = {};   // Qh*Kh
    float Sb[4][4] = {};   // Qh*Kl + Ql*Kh
#pragma unroll
    for (int kc = 0; kc < 4; ++kc) {
      u32 kh0[4], kh1[4], kl0[4], kl1[4];
      u32 ka = st + kc * 32 + k_lane;
      LDSM4(kh0, ka);                       // keys 0-15
      LDSM4(kh1, ka + 16 * 144);            // keys 16-31
      LDSM4(kl0, ka + 4608);
      LDSM4(kl1, ka + 4608 + 16 * 144);
      mma_f16(Sa[0], qfh[kc], kh0[0], kh0[1]);
      mma_f16(Sa[1], qfh[kc], kh0[2], kh0[3]);
      mma_f16(Sa[2], qfh[kc], kh1[0], kh1[1]);
      mma_f16(Sa[3], qfh[kc], kh1[2], kh1[3]);
      mma_f16(Sb[0], qfh[kc], kl0[0], kl0[1]);
      mma_f16(Sb[1], qfh[kc], kl0[2], kl0[3]);
      mma_f16(Sb[2], qfh[kc], kl1[0], kl1[1]);
      mma_f16(Sb[3], qfh[kc], kl1[2], kl1[3]);
      mma_f16(Sb[0], qfl[kc], kh0[0], kh0[1]);
      mma_f16(Sb[1], qfl[kc], kh0[2], kh0[3]);
      mma_f16(Sb[2], qfl[kc], kh1[0], kh1[1]);
      mma_f16(Sb[3], qfl[kc], kh1[2], kh1[3]);
    }
#pragma unroll
    for (int i = 0; i < 4; ++i)
#pragma unroll
      for (int e = 0; e < 4; ++e) Sa[i][e] += Sb[i][e];

    // ---- Scan on fragments: independent quad scans + prefix combine.
    //      W packed DIRECTLY into Phase-B A-fragments (C-frag == A-frag). ----
    u32 Wh[2][4], Wl[2][4];
#pragma unroll
    for (int half = 0; half < 2; ++half) {
      float bb = half ? carry1 : carry0;
      float run[4], tot[4];
#pragma unroll
      for (int nf = 0; nf < 4; ++nf) {
        float s0 = Sa[nf][half * 2], s1 = Sa[nf][half * 2 + 1];
        float r = s0 + s1;
        float n1 = __shfl_up_sync(FULL, r, 1, 4); if (qd >= 1) r += n1;
        float n2 = __shfl_up_sync(FULL, r, 2, 4); if (qd >= 2) r += n2;
        run[nf] = r;
        tot[nf] = __shfl_sync(FULL, r, 3, 4);
      }
      float base[4];
      base[0] = bb;
      base[1] = base[0] + tot[0];
      base[2] = base[1] + tot[1];
      base[3] = base[2] + tot[2];
      bb = base[3] + tot[3];
#pragma unroll
      for (int nf = 0; nf < 4; ++nf) {
        float s1 = Sa[nf][half * 2 + 1];
        float s0 = Sa[nf][half * 2];
        float cum1 = base[nf] + run[nf];
        float cum0 = cum1 - s1;
        float w0 = __fdividef(s0, fmaxf(cum0, 1e-6f));
        float w1 = __fdividef(s1, fmaxf(cum1, 1e-6f));
        u32 hw = packbf2(w0, w1);
        __nv_bfloat162 hv = *(__nv_bfloat162*)&hw;
        u32 lw = packbf2(w0 - __bfloat162float(hv.x),
                         w1 - __bfloat162float(hv.y));
        Wh[nf >> 1][((nf & 1) << 1) | half] = hw;
        Wl[nf >> 1][((nf & 1) << 1) | half] = lw;
      }
      if (half) carry1 = bb; else carry0 = bb;
    }

    // ---- Phase B: Y += W @ V (bf16x3, TERM-MAJOR per ng-pair) ----
    const u32 vst = st + 9216;
#pragma unroll
    for (int ks = 0; ks < 2; ++ks) {
#pragma unroll
      for (int np = 0; np < 2; ++np) {      // ng pair: (2np, 2np+1)
        u32 vh0[4], vl0[4], vh1[4], vl1[4];
        u32 va0 = vst + (2 * np) * 1280 + v_lane + ks * 32;
        u32 va1 = vst + (2 * np + 1) * 1280 + v_lane + ks * 32;
        LDSM4(vh0, va0);
        LDSM4(vl0, va0 + 5120);
        LDSM4(vh1, va1);
        LDSM4(vl1, va1 + 5120);
        float* y0 = Yacc[4 * np + 0];
        float* y1 = Yacc[4 * np + 1];
        float* y2 = Yacc[4 * np + 2];
        float* y3 = Yacc[4 * np + 3];
        // term h.h (4 independent)
        mma_bf16(y0, Wh[ks], vh0[0], vh0[1]);
        mma_bf16(y1, Wh[ks], vh0[2], vh0[3]);
        mma_bf16(y2, Wh[ks], vh1[0], vh1[1]);
        mma_bf16(y3, Wh[ks], vh1[2], vh1[3]);
        // term h.l (4 independent)
        mma_bf16(y0, Wh[ks], vl0[0], vl0[1]);
        mma_bf16(y1, Wh[ks], vl0[2], vl0[3]);
        mma_bf16(y2, Wh[ks], vl1[0], vl1[1]);
        mma_bf16(y3, Wh[ks], vl1[2], vl1[3]);
        // term l.h (4 independent)
        mma_bf16(y0, Wl[ks], vh0[0], vh0[1]);
        mma_bf16(y1, Wl[ks], vh0[2], vh0[3]);
        mma_bf16(y2, Wl[ks], vh1[0], vh1[1]);
        mma_bf16(y3, Wl[ks], vh1[2], vh1[3]);
      }
    }
  }

  // ---- Epilogue: split Y to bf16 hi/lo, store [t][C] ----
  const int row0 = q0 + w * 16 + g;
  const int colb = h * HD + 2 * qd;
#pragma unroll
  for (int nf = 0; nf < 8; ++nf) {
    int col = colb + nf * 8;
    size_t o0 = (size_t)row0 * CDIM + col;
    size_t o1 = (size_t)(row0 + 8) * CDIM + col;
    __nv_bfloat162 h2, l2;
    h2.x = __float2bfloat16(Yacc[nf][0]);
    l2.x = __float2bfloat16(Yacc[nf][0] - __bfloat162float(h2.x));
    h2.y = __float2bfloat16(Yacc[nf][1]);
    l2.y = __float2bfloat16(Yacc[nf][1] - __bfloat162float(h2.y));
    *(__nv_bfloat162*)&Yh_[o0] = h2;
    *(__nv_bfloat162*)&Yl_[o0] = l2;
    h2.x = __float2bfloat16(Yacc[nf][2]);
    l2.x = __float2bfloat16(Yacc[nf][2] - __bfloat162float(h2.x));
    h2.y = __float2bfloat16(Yacc[nf][3]);
    l2.y = __float2bfloat16(Yacc[nf][3] - __bfloat162float(h2.y));
    *(__nv_bfloat162*)&Yh_[o1] = h2;
    *(__nv_bfloat162*)&Yl_[o1] = l2;
  }
}

// ---------------------------------------------------------------------------
extern "C" void kernel_launch(void* const* d_in, const int* in_sizes, int n_in,
                              void* d_out, int out_size)
{
  const float* x      = (const float*)d_in[0];
  const float* w_attn = (const float*)d_in[1];
  const float* b_attn = (const float*)d_in[2];
  const float* w_proj = (const float*)d_in[3];
  const float* b_proj = (const float*)d_in[4];
  float* out = (float*)d_out;

  float* qkv;
  __half *xh, *xl, *wah, *wal, *qh, *ql, *kh, *kl;
  __nv_bfloat16 *wph, *wpl, *vbh, *vbl, *yh, *yl;
  cudaGetSymbolAddress((void**)&qkv, g_qkv);
  cudaGetSymbolAddress((void**)&xh,  g_xh);
  cudaGetSymbolAddress((void**)&xl,  g_xl);
  cudaGetSymbolAddress((void**)&wah, g_wah);
  cudaGetSymbolAddress((void**)&wal, g_wal);
  cudaGetSymbolAddress((void**)&wph, g_wph);
  cudaGetSymbolAddress((void**)&wpl, g_wpl);
  cudaGetSymbolAddress((void**)&qh,  g_qh);
  cudaGetSymbolAddress((void**)&ql,  g_ql);
  cudaGetSymbolAddress((void**)&kh,  g_kh);
  cudaGetSymbolAddress((void**)&kl,  g_kl);
  cudaGetSymbolAddress((void**)&vbh, g_vbh);
  cudaGetSymbolAddress((void**)&vbl, g_vbl);
  cudaGetSymbolAddress((void**)&yh,  g_yh);
  cudaGetSymbolAddress((void**)&yl,  g_yl);

  cudaFuncSetAttribute(gemm_f16,
                       cudaFuncAttributeMaxDynamicSharedMemorySize, GEMM_SMEM);
  cudaFuncSetAttribute(gemm_bf16,
                       cudaFuncAttributeMaxDynamicSharedMemorySize, GEMM_SMEM);
  cudaFuncSetAttribute(attn_mma,
                       cudaFuncAttributeMaxDynamicSharedMemorySize, ATT_SMEM);

  const int n4 = T_SEQ * CDIM / 4;

  // 0) conversions
  split_f16<<<(n4 + 255) / 256, 256>>>(x, xh, xl, n4);
  transpose_split_f16<<<dim3(K3 / 32, CDIM / 32), dim3(32, 8)>>>(
      w_attn, wah, wal, CDIM, K3);
  transpose_split_bf16<<<dim3(CDIM / 32, CDIM / 32), dim3(32, 8)>>>(
      w_proj, wph, wpl, CDIM, CDIM);

  // 1) qkv = x @ w_attn + b_attn   (fp16x3, term-major, 2 CTAs/SM)
  gemm_f16<<<dim3(K3 / 128, T_SEQ / 128), 256, GEMM_SMEM>>>(
      xh, xl, wah, wal, b_attn, qkv, T_SEQ, K3, CDIM);

  // 2) normalize + split q,k (fp16) and v (bf16, transposed)
  norm_split<<<dim3(T_SEQ / 64, NHEAD), 256>>>(qkv, qh, ql, kh, kl, vbh, vbl);

  // 3) tensorized cumulative linear attention -> yh/yl bf16
  attn_mma<<<dim3(T_SEQ / 128, NHEAD), 256, ATT_SMEM>>>(
      qh, ql, kh, kl, vbh, vbl, yh, yl);

  // 4) out = y @ w_proj + b_proj  (bf16x3, term-major, 2 CTAs/SM)
  gemm_bf16<<<dim3(CDIM / 128, T_SEQ / 128), 256, GEMM_SMEM>>>(
      yh, yl, wph, wpl, b_proj, out, T_SEQ, CDIM, CDIM);
}